// round 1
// baseline (speedup 1.0000x reference)
#include <cuda_runtime.h>
#include <cuda_bf16.h>
#include <stdint.h>

#define S 32
#define T 512
#define F 512
#define STEPS 12
#define NEG 32
#define C 33            // NEG + 1
#define NTHREADS 264    // 8 k-groups x 33 classes
#define TSTRIDE 516     // padded target row (floats), 16B-aligned rows
#define PSTRIDE 28      // padded P row (floats): 12 f32x2 pairs + pad, 16B-aligned

// smem layout (floats)
#define TS_OFF   0
#define PS_OFF   (C * TSTRIDE)                 // 17028
#define PART_OFF (PS_OFF + 256 * PSTRIDE)      // 24196
#define LOG_OFF  (PART_OFF + 8 * C * STEPS)    // 27364
#define ROW_OFF  (LOG_OFF + STEPS * 34)        // 27772 (ints)
#define RL_OFF   (ROW_OFF + 36)                // 27808
#define SMEM_FLOATS (RL_OFF + 16)              // 27824 -> 111296 B

// scratch (device globals: allocation-free rule)
__device__ __nv_bfloat16 g_predT[(size_t)S * STEPS * T * F]; // (s,i,t,f)  192 MB
__device__ __nv_bfloat16 g_latB[(size_t)S * T * F];          // bf16 latent 16 MB
__device__ float g_part[S * T];

// ---------------------------------------------------------------------------
// Kernel 1: latent fp32 -> bf16 copy (halves gather traffic in main kernel)
// ---------------------------------------------------------------------------
__global__ void latb_kernel(const float* __restrict__ lat) {
    const float2* in = (const float2*)lat;
    __nv_bfloat162* out = (__nv_bfloat162*)g_latB;
    int n2 = S * T * F / 2;
    for (int i = blockIdx.x * blockDim.x + threadIdx.x; i < n2;
         i += gridDim.x * blockDim.x) {
        float2 v = in[i];
        __nv_bfloat162 h;
        h.x = __float2bfloat16(v.x);
        h.y = __float2bfloat16(v.y);
        out[i] = h;
    }
}

// ---------------------------------------------------------------------------
// Kernel 2: transpose predictions (s,t,f,i) fp32 -> (s,i,t,f) bf16
// One block per (s,t): reads 24 KB contiguous, writes 12 coalesced bf16 rows.
// ---------------------------------------------------------------------------
__global__ void transpose_kernel(const float* __restrict__ pred) {
    __shared__ float sm[F * 13];   // pad 12->13 for conflict-free strided reads
    int st = blockIdx.x;           // s*T + t
    const float* in = pred + (size_t)st * (F * STEPS);
    for (int idx = threadIdx.x; idx < F * STEPS; idx += blockDim.x) {
        int f = idx / STEPS;
        int i = idx - f * STEPS;
        sm[f * 13 + i] = in[idx];
    }
    __syncthreads();
    int s = st >> 9;
    int t = st & (T - 1);
    // write pairs of f as bf16x2, coalesced per i-row
    for (int p = threadIdx.x; p < F * STEPS / 2; p += blockDim.x) {
        int i = p >> 8;            // / (F/2)
        int fp = p & 255;
        int f = fp * 2;
        __nv_bfloat162 h;
        h.x = __float2bfloat16(sm[f * 13 + i]);
        h.y = __float2bfloat16(sm[(f + 1) * 13 + i]);
        ((__nv_bfloat162*)(g_predT + ((size_t)((s * STEPS + i) * T + t)) * F))[fp] = h;
    }
}

// ---------------------------------------------------------------------------
// Kernel 3: main. One block per (s,u). Computes the 12x33 logit tile
// (12 complete softmax rows), logsumexp epilogue, per-block partial loss.
// ---------------------------------------------------------------------------
__global__ void __launch_bounds__(NTHREADS, 2)
main_kernel(const int* __restrict__ negi) {
    extern __shared__ float smf[];
    float* Tsh     = smf + TS_OFF;
    float* Psh     = smf + PS_OFF;
    float* part    = smf + PART_OFF;
    float* logits  = smf + LOG_OFF;
    int*   rowsm   = (int*)(smf + ROW_OFF);
    float* rowloss = smf + RL_OFF;

    const int u = blockIdx.x;
    const int s = blockIdx.y;
    const int tid = threadIdx.x;

    // --- target row indices (reference semantics: t_skip = flat_j / NEG) ---
    if (tid < C) {
        int row;
        if (tid == 0) {
            row = u;
        } else {
            int n = tid - 1;
            int j = n * T + u;
            int tsk = j >> 5;                     // j / NEG
            int raw = negi[s * (NEG * T) + j];
            row = raw + (raw >= tsk ? 1 : 0);
        }
        rowsm[tid] = row;
    }
    __syncthreads();

    // --- stage 33 target rows: bf16 gather from L2, f32 into smem ---
    const uint4* latu4 = (const uint4*)g_latB;     // 8 bf16 per uint4
    for (int x = tid; x < C * 64; x += NTHREADS) {
        int c2 = x >> 6;
        int q = x & 63;
        int row = rowsm[c2];
        uint4 raw = latu4[((size_t)(s * T + row)) * 64 + q];
        const __nv_bfloat162* b2 = (const __nv_bfloat162*)&raw;
        float2 v0 = __bfloat1622float2(b2[0]);
        float2 v1 = __bfloat1622float2(b2[1]);
        float2 v2 = __bfloat1622float2(b2[2]);
        float2 v3 = __bfloat1622float2(b2[3]);
        float* dst = Tsh + c2 * TSTRIDE + q * 8;
        *(float4*)(dst)     = make_float4(v0.x, v0.y, v1.x, v1.y);
        *(float4*)(dst + 4) = make_float4(v2.x, v2.y, v3.x, v3.y);
    }

    // --- stage 12 prediction rows into packed Psh[kp*PSTRIDE + 2i] ---
    const uint4* predu4 = (const uint4*)g_predT;
    for (int x = tid; x < STEPS * 64; x += NTHREADS) {
        int i = x >> 6;
        int q = x & 63;
        float2 v[4];
        if (i <= u) {
            uint4 raw = predu4[((size_t)((s * STEPS + i) * T + (u - i))) * 64 + q];
            const __nv_bfloat162* b2 = (const __nv_bfloat162*)&raw;
            v[0] = __bfloat1622float2(b2[0]);
            v[1] = __bfloat1622float2(b2[1]);
            v[2] = __bfloat1622float2(b2[2]);
            v[3] = __bfloat1622float2(b2[3]);
        } else {
            v[0] = v[1] = v[2] = v[3] = make_float2(0.f, 0.f);
        }
#pragma unroll
        for (int j2 = 0; j2 < 4; j2++)
            *(float2*)(Psh + (q * 4 + j2) * PSTRIDE + 2 * i) = v[j2];
    }
    __syncthreads();

    // --- tiny GEMM: thread = (kgroup, class). 12 f32x2 accumulators ---
    int kg = tid / C;            // 0..7 : K chunk of 64 floats (32 pairs)
    int c  = tid - kg * C;       // 0..32
    unsigned long long acc[STEPS];
#pragma unroll
    for (int i = 0; i < STEPS; i++) acc[i] = 0ULL;

    const float* tbase = Tsh + c * TSTRIDE + kg * 64;
    const float* pbase = Psh + (kg * 32) * PSTRIDE;
#pragma unroll 2
    for (int kp = 0; kp < 32; kp++) {
        unsigned long long tv = *(const unsigned long long*)(tbase + kp * 2);
        const ulonglong2* pr = (const ulonglong2*)(pbase + kp * PSTRIDE);
#pragma unroll
        for (int j = 0; j < 6; j++) {
            ulonglong2 pq = pr[j];
            asm("fma.rn.f32x2 %0, %1, %2, %0;" : "+l"(acc[2 * j])     : "l"(pq.x), "l"(tv));
            asm("fma.rn.f32x2 %0, %1, %2, %0;" : "+l"(acc[2 * j + 1]) : "l"(pq.y), "l"(tv));
        }
    }
#pragma unroll
    for (int i = 0; i < STEPS; i++) {
        float2 v = *(float2*)&acc[i];
        part[kg * (C * STEPS) + c * STEPS + i] = v.x + v.y;
    }
    __syncthreads();

    // --- reduce over 8 k-groups ---
    for (int o = tid; o < C * STEPS; o += NTHREADS) {
        int i = o / C;
        int c2 = o - i * C;
        float sum = 0.f;
#pragma unroll
        for (int g = 0; g < 8; g++) sum += part[g * (C * STEPS) + c2 * STEPS + i];
        logits[i * 34 + c2] = sum;
    }
    __syncthreads();

    // --- logsumexp epilogue: row (i, t=u-i, s) valid iff i <= u ---
    if (tid < STEPS) {
        float rl = 0.f;
        if (tid <= u) {
            const float* rowp = logits + tid * 34;
            float m = rowp[0];
#pragma unroll
            for (int c2 = 1; c2 < C; c2++) m = fmaxf(m, rowp[c2]);
            float sum = 0.f;
#pragma unroll
            for (int c2 = 0; c2 < C; c2++) sum += expf(rowp[c2] - m);
            rl = m + logf(sum) - rowp[0];
        }
        rowloss[tid] = rl;
    }
    __syncthreads();
    if (tid == 0) {
        float bl = 0.f;
#pragma unroll
        for (int i = 0; i < STEPS; i++) bl += rowloss[i];
        g_part[s * T + u] = bl;
    }
}

// ---------------------------------------------------------------------------
// Kernel 4: deterministic final reduction (no float atomics)
// ---------------------------------------------------------------------------
__global__ void reduce_kernel(float* __restrict__ out) {
    __shared__ float sm[512];
    int tid = threadIdx.x;
    float s0 = 0.f;
    for (int i = tid; i < S * T; i += 512) s0 += g_part[i];
    sm[tid] = s0;
    __syncthreads();
    for (int st = 256; st > 0; st >>= 1) {
        if (tid < st) sm[tid] += sm[tid + st];
        __syncthreads();
    }
    if (tid == 0) out[0] = sm[0];
}

extern "C" void kernel_launch(void* const* d_in, const int* in_sizes, int n_in,
                              void* d_out, int out_size) {
    const float* lat  = (const float*)d_in[0];
    const float* pred = (const float*)d_in[1];
    const int*   negi = (const int*)d_in[2];
    float* out = (float*)d_out;

    cudaFuncSetAttribute(main_kernel, cudaFuncAttributeMaxDynamicSharedMemorySize,
                         SMEM_FLOATS * 4);

    latb_kernel<<<2048, 256>>>(lat);
    transpose_kernel<<<S * T, 256>>>(pred);
    main_kernel<<<dim3(T, S), NTHREADS, SMEM_FLOATS * 4>>>(negi);
    reduce_kernel<<<1, 512>>>(out);
}

// round 2
// speedup vs baseline: 1.2061x; 1.2061x over previous
#include <cuda_runtime.h>
#include <cuda_bf16.h>
#include <stdint.h>

#define S 32
#define T 512
#define F 512
#define STEPS 12
#define NEG 32
#define C 33
#define NTH 256          // 8 warps; warp = one k-group (64 floats)
#define CP 34            // padded class count (float2 entries per kp row)
#define PST 28           // Ppack row stride in floats (24 used + pad, 16B-aligned rows)

// smem layout (floats)
#define T2_OFF   0                       // float2[256][34] -> 17408 floats
#define PP_OFF   17408                   // float [256][28] -> 7168 floats
#define LG_OFF   (PP_OFF + 7168)         // logits 396 (+pad 400)
#define RS_OFF   (LG_OFF + 400)          // rowsm 33 ints (+pad 48)
#define RL_OFF   (RS_OFF + 48)           // rowloss 12 (+pad 16)
#define SMEM_FLOATS (RL_OFF + 16)        // 25040 floats = 100160 B

__device__ __nv_bfloat16 g_predT[(size_t)S * STEPS * T * F]; // (s,i,t,f) bf16
__device__ __nv_bfloat16 g_latB[(size_t)S * T * F];          // bf16 latent
__device__ float g_part[S * T];

#define FMA2(a, b, t) asm("fma.rn.f32x2 %0, %1, %2, %0;" : "+l"(a) : "l"(b), "l"(t))

// ---------------------------------------------------------------------------
// Kernel 1: latent fp32 -> bf16
// ---------------------------------------------------------------------------
__global__ void latb_kernel(const float* __restrict__ lat) {
    const float2* in = (const float2*)lat;
    __nv_bfloat162* out = (__nv_bfloat162*)g_latB;
    int n2 = S * T * F / 2;
    for (int i = blockIdx.x * blockDim.x + threadIdx.x; i < n2;
         i += gridDim.x * blockDim.x) {
        float2 v = in[i];
        __nv_bfloat162 h;
        h.x = __float2bfloat16(v.x);
        h.y = __float2bfloat16(v.y);
        out[i] = h;
    }
}

// ---------------------------------------------------------------------------
// Kernel 2: transpose predictions (s,t,f,i) fp32 -> (s,i,t,f) bf16
// ---------------------------------------------------------------------------
__global__ void transpose_kernel(const float* __restrict__ pred) {
    __shared__ float sm[F * 13];
    int st = blockIdx.x;
    const float* in = pred + (size_t)st * (F * STEPS);
    for (int idx = threadIdx.x; idx < F * STEPS; idx += blockDim.x) {
        int f = idx / STEPS;
        int i = idx - f * STEPS;
        sm[f * 13 + i] = in[idx];
    }
    __syncthreads();
    int s = st >> 9;
    int t = st & (T - 1);
    for (int p = threadIdx.x; p < F * STEPS / 2; p += blockDim.x) {
        int i = p >> 8;
        int fp = p & 255;
        int f = fp * 2;
        __nv_bfloat162 h;
        h.x = __float2bfloat16(sm[f * 13 + i]);
        h.y = __float2bfloat16(sm[(f + 1) * 13 + i]);
        ((__nv_bfloat162*)(g_predT + ((size_t)((s * STEPS + i) * T + t)) * F))[fp] = h;
    }
}

// ---------------------------------------------------------------------------
// Kernel 3: main. One block per (s,u).
// Warp = k-group; lane l = negative class l+1; positive class via k-slivers.
// ---------------------------------------------------------------------------
__global__ void __launch_bounds__(NTH, 2)
main_kernel(const int* __restrict__ negi) {
    extern __shared__ float smf[];
    float2* T2     = (float2*)(smf + T2_OFF);   // [kp][class] float2
    float*  Pp     = smf + PP_OFF;              // [kp][24 packed + pad]
    float*  logits = smf + LG_OFF;
    int*    rowsm  = (int*)(smf + RS_OFF);
    float*  rowloss= smf + RL_OFF;
    float*  part   = smf;                       // alias T2 region (after barrier)

    const int u = blockIdx.x;
    const int s = blockIdx.y;
    const int tid = threadIdx.x;

    // target row indices
    if (tid < C) {
        int row;
        if (tid == 0) row = u;
        else {
            int j = (tid - 1) * T + u;
            int tsk = j >> 5;
            int raw = negi[s * (NEG * T) + j];
            row = raw + (raw >= tsk ? 1 : 0);
        }
        rowsm[tid] = row;
    }
    __syncthreads();

    // --- stage targets: 32B-granule gather, class-minor smem (conflict-free) ---
    const uint4* latu4 = (const uint4*)g_latB;
    for (int x = tid; x < C * 32; x += NTH) {
        int c  = x % C;
        int q2 = x / C;                       // 0..31, 16 k-values each
        size_t base = ((size_t)(s * T + rowsm[c])) * 64 + q2 * 2;
        uint4 ra = latu4[base];
        uint4 rb = latu4[base + 1];
        const __nv_bfloat162* ba = (const __nv_bfloat162*)&ra;
        const __nv_bfloat162* bb = (const __nv_bfloat162*)&rb;
#pragma unroll
        for (int j = 0; j < 4; j++)
            T2[(8 * q2 + j) * CP + c] = __bfloat1622float2(ba[j]);
#pragma unroll
        for (int j = 0; j < 4; j++)
            T2[(8 * q2 + 4 + j) * CP + c] = __bfloat1622float2(bb[j]);
    }

    // --- stage predictions: packed [kp][2i] layout, i-major lane mapping ---
    const uint4* pu4 = (const uint4*)g_predT;
    for (int x = tid; x < STEPS * 64; x += NTH) {
        int i = x % STEPS;
        int r = x / STEPS;                    // uint4 index 0..63
        float2 v[4];
        if (i <= u) {
            uint4 raw = pu4[((size_t)((s * STEPS + i) * T + (u - i))) * 64 + r];
            const __nv_bfloat162* b2 = (const __nv_bfloat162*)&raw;
            v[0] = __bfloat1622float2(b2[0]);
            v[1] = __bfloat1622float2(b2[1]);
            v[2] = __bfloat1622float2(b2[2]);
            v[3] = __bfloat1622float2(b2[3]);
        } else {
            v[0] = v[1] = v[2] = v[3] = make_float2(0.f, 0.f);
        }
#pragma unroll
        for (int j = 0; j < 4; j++)
            *(float2*)(Pp + (4 * r + j) * PST + 2 * i) = v[j];
    }
    __syncthreads();

    // --- GEMM: negatives (lane-parallel classes, broadcast P) ---
    const int kg = tid >> 5;
    const int l  = tid & 31;
    const int c  = l + 1;
    const int kb = kg * 32;

    unsigned long long acc[STEPS];
#pragma unroll
    for (int i = 0; i < STEPS; i++) acc[i] = 0ULL;

#pragma unroll 4
    for (int kp = 0; kp < 32; kp++) {
        int gk = kb + kp;
        unsigned long long tv = *(const unsigned long long*)(T2 + gk * CP + c);
        const ulonglong2* pr = (const ulonglong2*)(Pp + gk * PST);
#pragma unroll
        for (int j = 0; j < 6; j++) {
            ulonglong2 pq = pr[j];
            FMA2(acc[2 * j],     pq.x, tv);
            FMA2(acc[2 * j + 1], pq.y, tv);
        }
    }

    // --- positive class: k-sliver per lane ---
    unsigned long long accp[STEPS];
#pragma unroll
    for (int i = 0; i < STEPS; i++) accp[i] = 0ULL;
    {
        int gk = kb + l;
        unsigned long long tv0 = *(const unsigned long long*)(T2 + gk * CP);
        const float* pp0 = Pp + gk * PST;
#pragma unroll
        for (int i = 0; i < STEPS; i++) {
            unsigned long long pv = *(const unsigned long long*)(pp0 + 2 * i);
            FMA2(accp[i], pv, tv0);
        }
    }

    __syncthreads();   // all T2 reads complete before aliasing as 'part'

#pragma unroll
    for (int i = 0; i < STEPS; i++) {
        float2 v = *(float2*)&acc[i];
        part[kg * (STEPS * C) + i * C + c] = v.x + v.y;
    }
#pragma unroll
    for (int i = 0; i < STEPS; i++) {
        float2 v = *(float2*)&accp[i];
        float p = v.x + v.y;
        p += __shfl_down_sync(0xFFFFFFFFu, p, 16);
        p += __shfl_down_sync(0xFFFFFFFFu, p, 8);
        p += __shfl_down_sync(0xFFFFFFFFu, p, 4);
        p += __shfl_down_sync(0xFFFFFFFFu, p, 2);
        p += __shfl_down_sync(0xFFFFFFFFu, p, 1);
        if (l == 0) part[kg * (STEPS * C) + i * C] = p;
    }
    __syncthreads();

    // --- reduce over 8 k-groups ---
    for (int o = tid; o < STEPS * C; o += NTH) {
        float ssum = 0.f;
#pragma unroll
        for (int g = 0; g < 8; g++) ssum += part[g * (STEPS * C) + o];
        logits[o] = ssum;
    }
    __syncthreads();

    // --- logsumexp epilogue: row i valid iff i <= u ---
    if (tid < STEPS) {
        float rl = 0.f;
        if (tid <= u) {
            const float* rowp = logits + tid * C;
            float m = rowp[0];
#pragma unroll
            for (int c2 = 1; c2 < C; c2++) m = fmaxf(m, rowp[c2]);
            float sum = 0.f;
#pragma unroll
            for (int c2 = 0; c2 < C; c2++) sum += __expf(rowp[c2] - m);
            rl = m + __logf(sum) - rowp[0];
        }
        rowloss[tid] = rl;
    }
    __syncthreads();
    if (tid == 0) {
        float bl = 0.f;
#pragma unroll
        for (int i = 0; i < STEPS; i++) bl += rowloss[i];
        g_part[s * T + u] = bl;
    }
}

// ---------------------------------------------------------------------------
// Kernel 4: deterministic final reduction
// ---------------------------------------------------------------------------
__global__ void reduce_kernel(float* __restrict__ out) {
    __shared__ float sm[512];
    int tid = threadIdx.x;
    float s0 = 0.f;
    for (int i = tid; i < S * T; i += 512) s0 += g_part[i];
    sm[tid] = s0;
    __syncthreads();
    for (int st = 256; st > 0; st >>= 1) {
        if (tid < st) sm[tid] += sm[tid + st];
        __syncthreads();
    }
    if (tid == 0) out[0] = sm[0];
}

extern "C" void kernel_launch(void* const* d_in, const int* in_sizes, int n_in,
                              void* d_out, int out_size) {
    const float* lat  = (const float*)d_in[0];
    const float* pred = (const float*)d_in[1];
    const int*   negi = (const int*)d_in[2];
    float* out = (float*)d_out;

    cudaFuncSetAttribute(main_kernel, cudaFuncAttributeMaxDynamicSharedMemorySize,
                         SMEM_FLOATS * 4);

    latb_kernel<<<2048, 256>>>(lat);
    transpose_kernel<<<S * T, 256>>>(pred);
    main_kernel<<<dim3(T, S), NTH, SMEM_FLOATS * 4>>>(negi);
    reduce_kernel<<<1, 512>>>(out);
}

// round 4
// speedup vs baseline: 1.5602x; 1.2936x over previous
#include <cuda_runtime.h>
#include <cuda_bf16.h>
#include <stdint.h>

#define S 32
#define T 512
#define F 512
#define STEPS 12
#define NEG 32
#define C 33
#define NTH 256
#define TSU 258          // T row stride in u32 (256 used + 2 pad), ≡2 mod 32
#define PST 24           // Pp row stride in floats (exact 24)

// smem layout in 4-byte words
#define T_OFF    0                         // u32 [33][258] = 8514 (+2 pad)
#define PP_OFF   8516                      // f32 [256][24] = 6144
#define PART_OFF (PP_OFF + 6144)           // 14660: f32 [8][400] = 3200
#define LG_OFF   (PART_OFF + 3200)         // 17860: 396 (+4)
#define RS_OFF   (LG_OFF + 400)            // 18260: 33 (+3)
#define RL_OFF   (RS_OFF + 36)             // 18296: 12 (+4)
#define SMEM_WORDS (RL_OFF + 16)           // 18312 words = 73248 B (x3 = 219.7 KB/SM)

__device__ __nv_bfloat16 g_predT[(size_t)S * STEPS * T * F]; // (s,i,t,f)
__device__ __nv_bfloat16 g_latB[(size_t)S * T * F];
__device__ float g_part[S * T];

#define FMA2(a, b, t) asm("fma.rn.f32x2 %0, %1, %2, %0;" : "+l"(a) : "l"(b), "l"(t))

// bf16 (low/high 16 bits of u32) -> f32 bit pattern, on ALU pipe (PRMT)
__device__ __forceinline__ uint32_t bf_lo(uint32_t v) { return __byte_perm(v, 0, 0x1044); }
__device__ __forceinline__ uint32_t bf_hi(uint32_t v) { return __byte_perm(v, 0, 0x3244); }

__global__ void init_kernel() {
    if (blockIdx.x == 0 && threadIdx.x == 0) g_part[0] = 0.f;
}

// ---------------------------------------------------------------------------
// Kernel 1: latent fp32 -> bf16
// ---------------------------------------------------------------------------
__global__ void latb_kernel(const float* __restrict__ lat) {
    const float4* in = (const float4*)lat;
    uint2* out = (uint2*)g_latB;
    int n4 = S * T * F / 4;
    for (int i = blockIdx.x * blockDim.x + threadIdx.x; i < n4;
         i += gridDim.x * blockDim.x) {
        float4 v = in[i];
        __nv_bfloat162 a = __floats2bfloat162_rn(v.x, v.y);
        __nv_bfloat162 b = __floats2bfloat162_rn(v.z, v.w);
        uint2 h;
        h.x = *(uint32_t*)&a;
        h.y = *(uint32_t*)&b;
        out[i] = h;
    }
}

// ---------------------------------------------------------------------------
// Kernel 2: transpose predictions (s,t,f,i) fp32 -> (s,i,t,f) bf16
// ---------------------------------------------------------------------------
__global__ void transpose_kernel(const float* __restrict__ pred) {
    __shared__ float sm[F * 13];
    int st = blockIdx.x;
    const float4* in = (const float4*)(pred + (size_t)st * (F * STEPS));
    for (int x = threadIdx.x; x < F * STEPS / 4; x += blockDim.x) {
        float4 v = in[x];
        int idx = 4 * x;
#pragma unroll
        for (int e = 0; e < 4; e++) {
            int f = (idx + e) / STEPS;
            int i = (idx + e) - f * STEPS;
            sm[f * 13 + i] = ((const float*)&v)[e];
        }
    }
    __syncthreads();
    int s = st >> 9;
    int t = st & (T - 1);
    for (int p = threadIdx.x; p < STEPS * 128; p += blockDim.x) {
        int i = p >> 7;
        int fp2 = p & 127;
        int f = fp2 * 4;
        __nv_bfloat162 h0 = __floats2bfloat162_rn(sm[f * 13 + i], sm[(f + 1) * 13 + i]);
        __nv_bfloat162 h1 = __floats2bfloat162_rn(sm[(f + 2) * 13 + i], sm[(f + 3) * 13 + i]);
        uint2 h;
        h.x = *(uint32_t*)&h0;
        h.y = *(uint32_t*)&h1;
        ((uint2*)(g_predT + ((size_t)((s * STEPS + i) * T + t)) * F))[fp2] = h;
    }
}

// ---------------------------------------------------------------------------
// Kernel 3: main. One block per (s,u). Warp = k-group, lane = neg class l+1.
// T in smem as bf16 u32-per-k-pair; P in smem as f32 packed rows.
// ---------------------------------------------------------------------------
__global__ void __launch_bounds__(NTH, 3)
main_kernel(const int* __restrict__ negi) {
    extern __shared__ uint32_t smw[];
    uint32_t* Tw     = smw + T_OFF;              // [c][kp] u32 (bf16x2), stride TSU
    float*    Pp     = (float*)(smw + PP_OFF);   // [kp][2i] f32, stride PST
    float*    part   = (float*)(smw + PART_OFF);
    float*    logits = (float*)(smw + LG_OFF);
    int*      rowsm  = (int*)(smw + RS_OFF);
    float*    rowloss= (float*)(smw + RL_OFF);

    const int u = blockIdx.x;
    const int s = blockIdx.y;
    const int tid = threadIdx.x;

    if (tid < C) {
        int row;
        if (tid == 0) row = u;
        else {
            int j = (tid - 1) * T + u;
            int tsk = j >> 5;
            int raw = negi[s * (NEG * T) + j];
            row = raw + (raw >= tsk ? 1 : 0);
        }
        rowsm[tid] = row;
    }
    __syncthreads();

    // --- stage targets: raw bf16 copy, LDG.128 coalesced, STS.64 pairs ---
    const uint4* latu4 = (const uint4*)g_latB;
    for (int x = tid; x < C * 64; x += NTH) {
        int c = x >> 6;
        int q = x & 63;                          // uint4 = 4 k-pairs
        uint4 raw = latu4[((size_t)(s * T + rowsm[c])) * 64 + q];
        uint32_t* dst = Tw + c * TSU + 4 * q;
        *(uint2*)(dst)     = make_uint2(raw.x, raw.y);
        *(uint2*)(dst + 2) = make_uint2(raw.z, raw.w);
    }

    // --- stage predictions into Pp[kpair][2i] (f32, converted here) ---
    const uint4* pu4 = (const uint4*)g_predT;
    for (int x = tid; x < STEPS * 64; x += NTH) {
        int i = x % STEPS;
        int r = x / STEPS;
        float2 v[4];
        if (i <= u) {
            uint4 raw = pu4[((size_t)((s * STEPS + i) * T + (u - i))) * 64 + r];
            const uint32_t* w = (const uint32_t*)&raw;
#pragma unroll
            for (int j = 0; j < 4; j++) {
                v[j].x = __uint_as_float(bf_lo(w[j]));
                v[j].y = __uint_as_float(bf_hi(w[j]));
            }
        } else {
            v[0] = v[1] = v[2] = v[3] = make_float2(0.f, 0.f);
        }
#pragma unroll
        for (int j = 0; j < 4; j++)
            *(float2*)(Pp + (4 * r + j) * PST + 2 * i) = v[j];
    }
    __syncthreads();

    // --- GEMM: warp kg handles k-pairs kg*32..kg*32+31; lane = class l+1 ---
    const int kg = tid >> 5;
    const int l  = tid & 31;
    const int c  = l + 1;

    unsigned long long acc[STEPS];
#pragma unroll
    for (int i = 0; i < STEPS; i++) acc[i] = 0ULL;

    const uint32_t* tb = Tw + c * TSU + kg * 32;
    const float* pb = Pp + (kg * 32) * PST;
#pragma unroll 2
    for (int k2 = 0; k2 < 16; k2++) {            // 2 k-pairs per iter
        uint2 tr = *(const uint2*)(tb + 2 * k2); // conflict-free (TSU≡2 mod 32)
        unsigned long long tv0, tv1;
        asm("mov.b64 %0, {%1, %2};" : "=l"(tv0) : "r"(bf_lo(tr.x)), "r"(bf_hi(tr.x)));
        asm("mov.b64 %0, {%1, %2};" : "=l"(tv1) : "r"(bf_lo(tr.y)), "r"(bf_hi(tr.y)));
        const ulonglong2* pr0 = (const ulonglong2*)(pb + (2 * k2) * PST);
        const ulonglong2* pr1 = (const ulonglong2*)(pb + (2 * k2 + 1) * PST);
#pragma unroll
        for (int j = 0; j < 6; j++) {
            ulonglong2 pq = pr0[j];
            FMA2(acc[2 * j],     pq.x, tv0);
            FMA2(acc[2 * j + 1], pq.y, tv0);
        }
#pragma unroll
        for (int j = 0; j < 6; j++) {
            ulonglong2 pq = pr1[j];
            FMA2(acc[2 * j],     pq.x, tv1);
            FMA2(acc[2 * j + 1], pq.y, tv1);
        }
    }
#pragma unroll
    for (int i = 0; i < STEPS; i++) {
        float2 v = *(float2*)&acc[i];
        part[kg * 400 + i * C + c] = v.x + v.y;
    }

    // --- positive class: k-pair sliver per lane ---
    {
        unsigned long long accp[STEPS];
#pragma unroll
        for (int i = 0; i < STEPS; i++) accp[i] = 0ULL;
        uint32_t t0 = Tw[kg * 32 + l];           // class 0 row, kp = kg*32+l
        unsigned long long tv0;
        asm("mov.b64 %0, {%1, %2};" : "=l"(tv0) : "r"(bf_lo(t0)), "r"(bf_hi(t0)));
        const float* pp0 = Pp + (kg * 32 + l) * PST;
#pragma unroll
        for (int i = 0; i < STEPS; i++) {
            unsigned long long pv = *(const unsigned long long*)(pp0 + 2 * i);
            FMA2(accp[i], pv, tv0);
        }
#pragma unroll
        for (int i = 0; i < STEPS; i++) {
            float2 v = *(float2*)&accp[i];
            float p = v.x + v.y;
            p += __shfl_down_sync(0xFFFFFFFFu, p, 16);
            p += __shfl_down_sync(0xFFFFFFFFu, p, 8);
            p += __shfl_down_sync(0xFFFFFFFFu, p, 4);
            p += __shfl_down_sync(0xFFFFFFFFu, p, 2);
            p += __shfl_down_sync(0xFFFFFFFFu, p, 1);
            if (l == 0) part[kg * 400 + i * C] = p;
        }
    }
    __syncthreads();

    // --- reduce over 8 k-groups ---
    for (int o = tid; o < STEPS * C; o += NTH) {
        float ssum = 0.f;
#pragma unroll
        for (int g = 0; g < 8; g++) ssum += part[g * 400 + o];
        logits[o] = ssum;
    }
    __syncthreads();

    // --- logsumexp epilogue: row i valid iff i <= u ---
    if (tid < STEPS) {
        float rl = 0.f;
        if (tid <= u) {
            const float* rowp = logits + tid * C;
            float m = rowp[0];
#pragma unroll
            for (int c2 = 1; c2 < C; c2++) m = fmaxf(m, rowp[c2]);
            float sum = 0.f;
#pragma unroll
            for (int c2 = 0; c2 < C; c2++) sum += __expf(rowp[c2] - m);
            rl = m + __logf(sum) - rowp[0];
        }
        rowloss[tid] = rl;
    }
    __syncthreads();
    if (tid == 0) {
        float bl = 0.f;
#pragma unroll
        for (int i = 0; i < STEPS; i++) bl += rowloss[i];
        g_part[s * T + u] = bl;
    }
}

// ---------------------------------------------------------------------------
// Kernel 4: deterministic final reduction
// ---------------------------------------------------------------------------
__global__ void reduce_kernel(float* __restrict__ out) {
    __shared__ float sm[512];
    int tid = threadIdx.x;
    float s0 = 0.f;
    for (int i = tid; i < S * T; i += 512) s0 += g_part[i];
    sm[tid] = s0;
    __syncthreads();
    for (int st = 256; st > 0; st >>= 1) {
        if (tid < st) sm[tid] += sm[tid + st];
        __syncthreads();
    }
    if (tid == 0) out[0] = sm[0];
}

extern "C" void kernel_launch(void* const* d_in, const int* in_sizes, int n_in,
                              void* d_out, int out_size) {
    const float* lat  = (const float*)d_in[0];
    const float* pred = (const float*)d_in[1];
    const int*   negi = (const int*)d_in[2];
    float* out = (float*)d_out;

    cudaFuncSetAttribute(main_kernel, cudaFuncAttributeMaxDynamicSharedMemorySize,
                         SMEM_WORDS * 4);

    init_kernel<<<1, 32>>>();
    latb_kernel<<<1024, 256>>>(lat);
    transpose_kernel<<<S * T, 256>>>(pred);
    main_kernel<<<dim3(T, S), NTH, SMEM_WORDS * 4>>>(negi);
    reduce_kernel<<<1, 512>>>(out);
}

// round 5
// speedup vs baseline: 1.6823x; 1.0782x over previous
#include <cuda_runtime.h>
#include <cuda_bf16.h>
#include <stdint.h>

#define S 32
#define T 512
#define F 512
#define STEPS 12
#define NEG 32
#define C 33
#define NTH 256

// smem layout in 4-byte words
#define T_OFF    0                      // T: 33 classes x 256 u32 (bf16x2), XOR-swizzled
#define PP_OFF   8448                   // P: 256 rows x 24 f32
#define PART_OFF (PP_OFF + 6144)        // 14592: 8 kg x 400
#define LG_OFF   (PART_OFF + 3200)      // 17792: 396 (+4)
#define RS_OFF   (LG_OFF + 400)         // 18192: 33 (+3)
#define RL_OFF   (RS_OFF + 36)          // 18228: 12 (+4)
#define SMEM_WORDS (RL_OFF + 16)        // 18244 words = 72976 B (x3 = 218.9 KB/SM)

__device__ __nv_bfloat16 g_predT[(size_t)S * STEPS * T * F]; // (s,i,t,f)
__device__ __nv_bfloat16 g_latB[(size_t)S * T * F];
__device__ float g_part[S * T];

#define FMA2(a, b, t) asm("fma.rn.f32x2 %0, %1, %2, %0;" : "+l"(a) : "l"(b), "l"(t))

__device__ __forceinline__ uint32_t bf_lo(uint32_t v) { return __byte_perm(v, 0, 0x1044); }
__device__ __forceinline__ uint32_t bf_hi(uint32_t v) { return __byte_perm(v, 0, 0x3244); }

__global__ void init_kernel() {
    if (blockIdx.x == 0 && threadIdx.x == 0) g_part[0] = 0.f;
}

// ---------------------------------------------------------------------------
// Kernel 1: latent fp32 -> bf16
// ---------------------------------------------------------------------------
__global__ void latb_kernel(const float* __restrict__ lat) {
    const float4* in = (const float4*)lat;
    uint2* out = (uint2*)g_latB;
    int n4 = S * T * F / 4;
    for (int i = blockIdx.x * blockDim.x + threadIdx.x; i < n4;
         i += gridDim.x * blockDim.x) {
        float4 v = in[i];
        __nv_bfloat162 a = __floats2bfloat162_rn(v.x, v.y);
        __nv_bfloat162 b = __floats2bfloat162_rn(v.z, v.w);
        uint2 h;
        h.x = *(uint32_t*)&a;
        h.y = *(uint32_t*)&b;
        out[i] = h;
    }
}

// ---------------------------------------------------------------------------
// Kernel 2: transpose predictions (s,t,f,i) fp32 -> (s,i,t,f) bf16
// ---------------------------------------------------------------------------
__global__ void transpose_kernel(const float* __restrict__ pred) {
    __shared__ float sm[F * 13];
    int st = blockIdx.x;
    const float4* in = (const float4*)(pred + (size_t)st * (F * STEPS));
    for (int x = threadIdx.x; x < F * STEPS / 4; x += blockDim.x) {
        float4 v = in[x];
        int idx = 4 * x;
#pragma unroll
        for (int e = 0; e < 4; e++) {
            int f = (idx + e) / STEPS;
            int i = (idx + e) - f * STEPS;
            sm[f * 13 + i] = ((const float*)&v)[e];
        }
    }
    __syncthreads();
    int s = st >> 9;
    int t = st & (T - 1);
    for (int p = threadIdx.x; p < STEPS * 128; p += blockDim.x) {
        int i = p >> 7;
        int fp2 = p & 127;
        int f = fp2 * 4;
        __nv_bfloat162 h0 = __floats2bfloat162_rn(sm[f * 13 + i], sm[(f + 1) * 13 + i]);
        __nv_bfloat162 h1 = __floats2bfloat162_rn(sm[(f + 2) * 13 + i], sm[(f + 3) * 13 + i]);
        uint2 h;
        h.x = *(uint32_t*)&h0;
        h.y = *(uint32_t*)&h1;
        ((uint2*)(g_predT + ((size_t)((s * STEPS + i) * T + t)) * F))[fp2] = h;
    }
}

// ---------------------------------------------------------------------------
// Kernel 3: main. One block per (s,u).
// warp = k-group (64 floats); lane = (cl, ksub): classes cl+1 & cl+17 over
// 16 k-pairs. T bf16 XOR-swizzled; P f32 rows of 24 with quarter rotation.
// ---------------------------------------------------------------------------
__global__ void __launch_bounds__(NTH, 3)
main_kernel(const int* __restrict__ negi) {
    extern __shared__ uint32_t smw[];
    uint32_t* Tw     = smw + T_OFF;
    float*    Pp     = (float*)(smw + PP_OFF);
    float*    part   = (float*)(smw + PART_OFF);
    float*    logits = (float*)(smw + LG_OFF);
    int*      rowsm  = (int*)(smw + RS_OFF);
    float*    rowloss= (float*)(smw + RL_OFF);

    const int u = blockIdx.x;
    const int s = blockIdx.y;
    const int tid = threadIdx.x;

    if (tid < C) {
        int row;
        if (tid == 0) row = u;
        else {
            int j = (tid - 1) * T + u;
            int tsk = j >> 5;
            int raw = negi[s * (NEG * T) + j];
            row = raw + (raw >= tsk ? 1 : 0);
        }
        rowsm[tid] = row;
    }
    __syncthreads();

    // --- stage targets: bf16 copy, XOR-swizzled 16B granules, STS.128 ---
    const uint4* latu4 = (const uint4*)g_latB;
    for (int x = tid; x < C * 64; x += NTH) {
        int c = x >> 6;
        int q = x & 63;                     // 16B granule = 4 k-pairs
        uint4 raw = latu4[((size_t)(s * T + rowsm[c])) * 64 + q];
        *(uint4*)(Tw + c * 256 + ((q ^ (c & 7)) << 2)) = raw;
    }

    // --- stage predictions into Pp[row=kpair][2i] f32 ---
    const uint4* pu4 = (const uint4*)g_predT;
    for (int x = tid; x < STEPS * 64; x += NTH) {
        int i = x % STEPS;
        int r = x / STEPS;
        float2 v[4];
        if (i <= u) {
            uint4 raw = pu4[((size_t)((s * STEPS + i) * T + (u - i))) * 64 + r];
            const uint32_t* w = (const uint32_t*)&raw;
#pragma unroll
            for (int j = 0; j < 4; j++) {
                v[j].x = __uint_as_float(bf_lo(w[j]));
                v[j].y = __uint_as_float(bf_hi(w[j]));
            }
        } else {
            v[0] = v[1] = v[2] = v[3] = make_float2(0.f, 0.f);
        }
#pragma unroll
        for (int j = 0; j < 4; j++)
            *(float2*)(Pp + (4 * r + j) * 24 + 2 * i) = v[j];
    }
    __syncthreads();

    // --- GEMM ---
    const int kg   = tid >> 5;
    const int l    = tid & 31;
    const int cl   = l & 15;
    const int ksub = l >> 4;
    const int c0   = cl + 1;              // second class = c0 + 16
    const int sw   = c0 & 7;              // same for c0 and c0+16
    const int gbase = kg * 8 + ksub * 4;  // T granule base
    const int rbase = kg * 32 + ksub * 16;// P row base
    const int koff  = 12 * ksub;          // quarter rotation offset

    unsigned long long a0[STEPS], a1[STEPS];
#pragma unroll
    for (int i = 0; i < STEPS; i++) { a0[i] = 0ULL; a1[i] = 0ULL; }

#pragma unroll
    for (int m = 0; m < 4; m++) {
        int tix = ((gbase + m) ^ sw) << 2;
        uint4 tq0 = *(const uint4*)(Tw + c0 * 256 + tix);
        uint4 tq1 = *(const uint4*)(Tw + (c0 + 16) * 256 + tix);
#pragma unroll
        for (int kk = 0; kk < 4; kk++) {
            int r = rbase + 4 * m + kk;
            const float* pA = Pp + r * 24 + koff;   // quarters 0..2 (local)
            const float* pB = pA - 2 * koff;        // quarters 3..5 (local)
            uint32_t w0 = ((const uint32_t*)&tq0)[kk];
            uint32_t w1 = ((const uint32_t*)&tq1)[kk];
            unsigned long long tv0, tv1;
            asm("mov.b64 %0, {%1, %2};" : "=l"(tv0) : "r"(bf_lo(w0)), "r"(bf_hi(w0)));
            asm("mov.b64 %0, {%1, %2};" : "=l"(tv1) : "r"(bf_lo(w1)), "r"(bf_hi(w1)));
#pragma unroll
            for (int q = 0; q < 3; q++) {
                ulonglong2 pq = *(const ulonglong2*)(pA + 4 * q);
                FMA2(a0[2 * q],     pq.x, tv0);
                FMA2(a0[2 * q + 1], pq.y, tv0);
                FMA2(a1[2 * q],     pq.x, tv1);
                FMA2(a1[2 * q + 1], pq.y, tv1);
            }
#pragma unroll
            for (int q = 3; q < 6; q++) {
                ulonglong2 pq = *(const ulonglong2*)(pB + 4 * q);
                FMA2(a0[2 * q],     pq.x, tv0);
                FMA2(a0[2 * q + 1], pq.y, tv0);
                FMA2(a1[2 * q],     pq.x, tv1);
                FMA2(a1[2 * q + 1], pq.y, tv1);
            }
        }
    }

    // pair-sum (local quarter order)
    float s0[STEPS], s1[STEPS];
#pragma unroll
    for (int i = 0; i < STEPS; i++) {
        float2 v0 = *(float2*)&a0[i];
        float2 v1 = *(float2*)&a1[i];
        s0[i] = v0.x + v0.y;
        s1[i] = v1.x + v1.y;
    }
    // combine ksub halves: partner's local quarter (q+3)%6 = my logical quarter
    float r0[STEPS], r1[STEPS];
#pragma unroll
    for (int q = 0; q < 6; q++) {
        const int qp = (q + 3) % 6;       // compile-time
        r0[2 * q]     = s0[2 * q]     + __shfl_xor_sync(0xFFFFFFFFu, s0[2 * qp], 16);
        r0[2 * q + 1] = s0[2 * q + 1] + __shfl_xor_sync(0xFFFFFFFFu, s0[2 * qp + 1], 16);
        r1[2 * q]     = s1[2 * q]     + __shfl_xor_sync(0xFFFFFFFFu, s1[2 * qp], 16);
        r1[2 * q + 1] = s1[2 * q + 1] + __shfl_xor_sync(0xFFFFFFFFu, s1[2 * qp + 1], 16);
    }
    if (ksub == 0) {                      // lane local order == logical order
#pragma unroll
        for (int i = 0; i < STEPS; i++) {
            part[kg * 400 + i * C + c0]      = r0[i];
            part[kg * 400 + i * C + c0 + 16] = r1[i];
        }
    }

    // --- positive class: one P row per lane ---
    {
        unsigned long long ap[STEPS];
#pragma unroll
        for (int i = 0; i < STEPS; i++) ap[i] = 0ULL;
        uint32_t t0w = Tw[kg * 32 + l];   // class 0: swizzle is identity
        unsigned long long tv0;
        asm("mov.b64 %0, {%1, %2};" : "=l"(tv0) : "r"(bf_lo(t0w)), "r"(bf_hi(t0w)));
        const ulonglong2* pp = (const ulonglong2*)(Pp + (kg * 32 + l) * 24);
#pragma unroll
        for (int j = 0; j < 6; j++) {
            ulonglong2 pq = pp[j];
            FMA2(ap[2 * j],     pq.x, tv0);
            FMA2(ap[2 * j + 1], pq.y, tv0);
        }
#pragma unroll
        for (int i = 0; i < STEPS; i++) {
            float2 v = *(float2*)&ap[i];
            float p = v.x + v.y;
            p += __shfl_down_sync(0xFFFFFFFFu, p, 16);
            p += __shfl_down_sync(0xFFFFFFFFu, p, 8);
            p += __shfl_down_sync(0xFFFFFFFFu, p, 4);
            p += __shfl_down_sync(0xFFFFFFFFu, p, 2);
            p += __shfl_down_sync(0xFFFFFFFFu, p, 1);
            if (l == 0) part[kg * 400 + i * C] = p;
        }
    }
    __syncthreads();

    // --- reduce over 8 k-groups ---
    for (int o = tid; o < STEPS * C; o += NTH) {
        float ssum = 0.f;
#pragma unroll
        for (int g = 0; g < 8; g++) ssum += part[g * 400 + o];
        logits[o] = ssum;
    }
    __syncthreads();

    // --- logsumexp epilogue: row i valid iff i <= u ---
    if (tid < STEPS) {
        float rl = 0.f;
        if (tid <= u) {
            const float* rowp = logits + tid * C;
            float m = rowp[0];
#pragma unroll
            for (int c2 = 1; c2 < C; c2++) m = fmaxf(m, rowp[c2]);
            float sum = 0.f;
#pragma unroll
            for (int c2 = 0; c2 < C; c2++) sum += __expf(rowp[c2] - m);
            rl = m + __logf(sum) - rowp[0];
        }
        rowloss[tid] = rl;
    }
    __syncthreads();
    if (tid == 0) {
        float bl = 0.f;
#pragma unroll
        for (int i = 0; i < STEPS; i++) bl += rowloss[i];
        g_part[s * T + u] = bl;
    }
}

// ---------------------------------------------------------------------------
// Kernel 4: deterministic final reduction
// ---------------------------------------------------------------------------
__global__ void reduce_kernel(float* __restrict__ out) {
    __shared__ float sm[512];
    int tid = threadIdx.x;
    float s0 = 0.f;
    for (int i = tid; i < S * T; i += 512) s0 += g_part[i];
    sm[tid] = s0;
    __syncthreads();
    for (int st = 256; st > 0; st >>= 1) {
        if (tid < st) sm[tid] += sm[tid + st];
        __syncthreads();
    }
    if (tid == 0) out[0] = sm[0];
}

extern "C" void kernel_launch(void* const* d_in, const int* in_sizes, int n_in,
                              void* d_out, int out_size) {
    const float* lat  = (const float*)d_in[0];
    const float* pred = (const float*)d_in[1];
    const int*   negi = (const int*)d_in[2];
    float* out = (float*)d_out;

    cudaFuncSetAttribute(main_kernel, cudaFuncAttributeMaxDynamicSharedMemorySize,
                         SMEM_WORDS * 4);

    init_kernel<<<1, 32>>>();
    latb_kernel<<<1024, 256>>>(lat);
    transpose_kernel<<<S * T, 256>>>(pred);
    main_kernel<<<dim3(T, S), NTH, SMEM_WORDS * 4>>>(negi);
    reduce_kernel<<<1, 512>>>(out);
}